// round 15
// baseline (speedup 1.0000x reference)
#include <cuda_runtime.h>

// B=4, T=32, C=512, ENC=32, DIM=1024, N_PAIRS=4096
// Output: Re(final_state), float32[4194304], idx = P*1024 + da'*32 + db'.
//
// Rank-8 factorization of the whole circuit (see R11): for each pair (i,j)
//   out[da',db'] = sum_{k=0..7} A_k[da'] * B_k[db']
// with per-row factor tables g_A/g_B built once in enc_kernel.

typedef unsigned long long ull;

__device__ float g_A[128][32][8];   // [row][da'][k]: k0..3 = Are, k4..7 = -Aim
__device__ float g_B[128][32][8];   // [row][db'][k]: k0..3 = Bre, k4..7 = +Bim

__device__ __forceinline__ ull pk2(float lo, float hi) {
    ull r; asm("mov.b64 %0, {%1, %2};" : "=l"(r) : "f"(lo), "f"(hi)); return r;
}
__device__ __forceinline__ void unpk2(ull v, float& lo, float& hi) {
    asm("mov.b64 {%0, %1}, %2;" : "=f"(lo), "=f"(hi) : "l"(v));
}
__device__ __forceinline__ ull fma2(ull a, ull b, ull c) {
    ull d; asm("fma.rn.f32x2 %0, %1, %2, %3;" : "=l"(d) : "l"(a), "l"(b), "l"(c)); return d;
}
__device__ __forceinline__ ull mul2(ull a, ull b) {
    ull d; asm("mul.rn.f32x2 %0, %1, %2;" : "=l"(d) : "l"(a), "l"(b)); return d;
}

// Complex 2x2 gate G = RY(ty)*RX(tx) as a shfl butterfly inside one warp.
__device__ __forceinline__ float2 gate_shfl_c(float2 v, int lane, int mask,
                                              float tx, float ty) {
    float cx, sx, cy, sy;
    sincosf(0.5f * tx, &sx, &cx);
    sincosf(0.5f * ty, &sy, &cy);
    float ox = __shfl_xor_sync(0xffffffffu, v.x, mask);
    float oy = __shfl_xor_sync(0xffffffffu, v.y, mask);
    bool hi = (lane & mask) != 0;
    float mdx = cy * cx,                 mdy = hi ? -sy * sx : sy * sx;
    float mox = hi ? sy * cx : -sy * cx, moy = -cy * sx;
    float2 r;
    r.x = mdx * v.x - mdy * v.y + mox * ox - moy * oy;
    r.y = mdx * v.y + mdy * v.x + mox * oy + moy * ox;
    return r;
}

__device__ __forceinline__ void ry_round(float& ur, float& ui, int lane,
                                         int mask, float c, float s) {
    float orr = __shfl_xor_sync(0xffffffffu, ur, mask);
    float oi  = __shfl_xor_sync(0xffffffffu, ui, mask);
    if (lane & mask) {
        ur = fmaf(s, orr,  c * ur);
        ui = fmaf(s, oi,   c * ui);
    } else {
        ur = fmaf(-s, orr, c * ur);
        ui = fmaf(-s, oi,  c * ui);
    }
}

// enc = L2norm(x @ W^T + b); layer-1 gates; 8 factor-chains on 8 warps.
__global__ void __launch_bounds__(256) enc_kernel(
    const float* __restrict__ x, const float* __restrict__ W,
    const float* __restrict__ bias, const float* __restrict__ trx,
    const float* __restrict__ try0, const float* __restrict__ try1) {
    int row = blockIdx.x;            // 0..127
    __shared__ float part[32][8];
    __shared__ float2 a_sh[32], b_sh[32];
    int tid = threadIdx.x, wid = tid >> 5, lane = tid & 31;
    int j = tid >> 3, p = tid & 7;
    const float4* xr = (const float4*)(x + row * 512 + p * 64);
    const float4* wr = (const float4*)(W + j * 512 + p * 64);
    float s = 0.f;
#pragma unroll
    for (int k = 0; k < 16; k++) {
        float4 xv = xr[k], wv = wr[k];
        s = fmaf(xv.x, wv.x, s); s = fmaf(xv.y, wv.y, s);
        s = fmaf(xv.z, wv.z, s); s = fmaf(xv.w, wv.w, s);
    }
    part[j][p] = s;
    __syncthreads();

    if (wid < 2) {
        float acc = bias[lane];
#pragma unroll
        for (int q = 0; q < 8; q++) acc += part[lane][q];
        float sq = acc * acc;
#pragma unroll
        for (int o = 16; o; o >>= 1) sq += __shfl_xor_sync(0xffffffffu, sq, o);
        float v = acc * rsqrtf(sq);
        float2 u = make_float2(v, 0.f);
        int toff = (wid == 0) ? 0 : 5;
#pragma unroll
        for (int w = 0; w < 5; w++)
            u = gate_shfl_c(u, lane, 16 >> w, trx[w + toff], try0[w + toff]);
        if (wid == 0) a_sh[lane] = u; else b_sh[lane] = u;
    }
    __syncthreads();

    {   // one factor-combo per warp
        int side = (wid >> 2) & 1, sel = (wid >> 1) & 1, off = wid & 1;
        float cw[5], sw[5];
#pragma unroll
        for (int w = 0; w < 5; w++)
            sincosf(0.5f * try1[w + 5 * side], &sw[w], &cw[w]);
        int gray = lane ^ (lane >> 1);
        int src = gray ^ (off ? (side ? 16 : 24) : 0);
        float2 uin = side ? b_sh[src] : a_sh[src];
        float ur = uin.x, ui = uin.y;
        if ((lane & 1) != sel) { ur = 0.f; ui = 0.f; }
#pragma unroll
        for (int w = 0; w < 5; w++)
            ry_round(ur, ui, lane, 16 >> w, cw[w], sw[w]);
        if (side == 0) {
            int k = 2 * sel + off;
            g_A[row][lane][k] = ur;
            g_A[row][lane][4 + k] = -ui;
        } else {
            int k = 2 * off + sel;
            g_B[row][lane][k] = ur;
            g_B[row][lane][4 + k] = ui;
        }
    }
}

// Pair kernel v6: STG.128 stores + f32x2 dot math.
// Block = 128 thr = 4 warps, covers 2 pairs (same a-row, j and j+1).
// Warp: pair pj = wid>>1, row-half mh = wid&1 (rows 16mh..16mh+15).
// Lane: r = lane>>3 (row within 4-row group), cg = lane&7 (4 cols = 4*cg..+3).
__global__ void __launch_bounds__(128) pair_kernel(
    float* __restrict__ out, unsigned int n_out_f32) {
    __shared__ float4 As[64];            // A factors of a-row: [da'][re4|im4]
    __shared__ float4 Bs[2][64];         // B factors of the 2 b-rows
    int tid = threadIdx.x, wid = tid >> 5, lane = tid & 31;
    int P0 = blockIdx.x * 2;
    int bb = P0 >> 10;
    int i = (P0 >> 5) & 31;
    int jb = P0 & 31;                    // even
    int rowA = bb * 32 + i;
    if (tid < 64) As[tid] = ((const float4*)g_A[rowA])[tid];
    {
        int pj = tid >> 6, idx = tid & 63;
        Bs[pj][idx] = ((const float4*)g_B[bb * 32 + jb + pj])[idx];
    }
    __syncthreads();

    int pj = wid >> 1, mh = wid & 1;
    int r = lane >> 3, cg = lane & 7;

    // Pack B for this thread's 4 columns (c0..c3) into f32x2 pairs:
    // Bp01[k] = {B[c0][k], B[c1][k]},  Bp23[k] = {B[c2][k], B[c3][k]}
    ull Bp01[8], Bp23[8];
    {
        const float4* bq = Bs[pj] + cg * 8;   // 4 cols x 2 float4
        float4 c0a = bq[0], c0b = bq[1], c1a = bq[2], c1b = bq[3];
        float4 c2a = bq[4], c2b = bq[5], c3a = bq[6], c3b = bq[7];
        Bp01[0] = pk2(c0a.x, c1a.x); Bp01[1] = pk2(c0a.y, c1a.y);
        Bp01[2] = pk2(c0a.z, c1a.z); Bp01[3] = pk2(c0a.w, c1a.w);
        Bp01[4] = pk2(c0b.x, c1b.x); Bp01[5] = pk2(c0b.y, c1b.y);
        Bp01[6] = pk2(c0b.z, c1b.z); Bp01[7] = pk2(c0b.w, c1b.w);
        Bp23[0] = pk2(c2a.x, c3a.x); Bp23[1] = pk2(c2a.y, c3a.y);
        Bp23[2] = pk2(c2a.z, c3a.z); Bp23[3] = pk2(c2a.w, c3a.w);
        Bp23[4] = pk2(c2b.x, c3b.x); Bp23[5] = pk2(c2b.y, c3b.y);
        Bp23[6] = pk2(c2b.z, c3b.z); Bp23[7] = pk2(c2b.w, c3b.w);
    }

    int P = P0 + pj;
    bool full = ((unsigned int)(P0 + 2) * 1024u <= n_out_f32);
    float* op = out + (size_t)P * 1024;

#pragma unroll
    for (int it = 0; it < 4; it++) {
        int m = (mh << 4) | (it << 2) | r;
        float4 ar = As[2 * m], ai = As[2 * m + 1];
        ull a0 = pk2(ar.x, ar.x), a1 = pk2(ar.y, ar.y);
        ull a2 = pk2(ar.z, ar.z), a3 = pk2(ar.w, ar.w);
        ull a4 = pk2(ai.x, ai.x), a5 = pk2(ai.y, ai.y);
        ull a6 = pk2(ai.z, ai.z), a7 = pk2(ai.w, ai.w);
        ull acc01 = mul2(a0, Bp01[0]);
        ull acc23 = mul2(a0, Bp23[0]);
        acc01 = fma2(a1, Bp01[1], acc01);  acc23 = fma2(a1, Bp23[1], acc23);
        acc01 = fma2(a2, Bp01[2], acc01);  acc23 = fma2(a2, Bp23[2], acc23);
        acc01 = fma2(a3, Bp01[3], acc01);  acc23 = fma2(a3, Bp23[3], acc23);
        acc01 = fma2(a4, Bp01[4], acc01);  acc23 = fma2(a4, Bp23[4], acc23);
        acc01 = fma2(a5, Bp01[5], acc01);  acc23 = fma2(a5, Bp23[5], acc23);
        acc01 = fma2(a6, Bp01[6], acc01);  acc23 = fma2(a6, Bp23[6], acc23);
        acc01 = fma2(a7, Bp01[7], acc01);  acc23 = fma2(a7, Bp23[7], acc23);
        float v0, v1, v2, v3;
        unpk2(acc01, v0, v1);
        unpk2(acc23, v2, v3);
        int eidx = (m << 5) | (cg << 2);          // element offset in pair
        if (full) {
            *(float4*)(op + eidx) = make_float4(v0, v1, v2, v3);
        } else {
            unsigned int gbase = (unsigned int)P * 1024u + (unsigned int)eidx;
            if (gbase + 0 < n_out_f32) op[eidx + 0] = v0;
            if (gbase + 1 < n_out_f32) op[eidx + 1] = v1;
            if (gbase + 2 < n_out_f32) op[eidx + 2] = v2;
            if (gbase + 3 < n_out_f32) op[eidx + 3] = v3;
        }
    }
}

__global__ void zero_kernel(float* out, unsigned int n_floats) {
    unsigned int i = blockIdx.x * blockDim.x + threadIdx.x;
    if (i < n_floats) out[i] = 0.f;
}

extern "C" void kernel_launch(void* const* d_in, const int* in_sizes, int n_in,
                              void* d_out, int out_size) {
    long mx = 0;
    for (int i = 0; i < n_in; i++) if (in_sizes[i] > mx) mx = in_sizes[i];
    int div = (mx == 262144) ? 4 : 1;

    const float* x = 0; const float* W = 0; const float* bias = 0;
    const float* th[3] = {0, 0, 0};
    int nth = 0;
    for (int i = 0; i < n_in; i++) {
        long s = in_sizes[i] / div;
        const float* p = (const float*)d_in[i];
        if (s == 65536)      x = p;
        else if (s == 16384) W = p;
        else if (s == 32)    bias = p;
        else if (s == 10 && nth < 3) th[nth++] = p;
    }
    if (!x || !W || !bias || nth < 3) {
        if (n_in >= 6) {
            x = (const float*)d_in[0]; W = (const float*)d_in[1];
            bias = (const float*)d_in[2];
            th[0] = (const float*)d_in[3]; th[1] = (const float*)d_in[4];
            th[2] = (const float*)d_in[5];
        } else {
            zero_kernel<<<(out_size + 255) / 256, 256>>>((float*)d_out,
                                                         (unsigned int)out_size);
            return;
        }
    }

    enc_kernel<<<128, 256>>>(x, W, bias, th[0], th[1], th[2]);
    pair_kernel<<<2048, 128>>>((float*)d_out, (unsigned int)out_size);
}